// round 14
// baseline (speedup 1.0000x reference)
#include <cuda_runtime.h>
#include <cuda_bf16.h>
#include <cstdint>
#include <cmath>

// Problem constants
static constexpr int B  = 4;
static constexpr int T  = 2048;
static constexpr int C  = 1024;
static constexpr int H  = 16;
static constexpr int HD = 64;
static constexpr int M1  = B * T;      // 8192
static constexpr int N1  = 3 * C;      // 3072
static constexpr int BTC = B * T * C;  // 8388608

// Scratch
__device__ float g_q[BTC];    // q in [B,H,T,HD], pre-scaled by 1/8
__device__ float g_att[BTC];  // attention output in [B,T,C]

// bf16 m16n8k16 MMA, fp32 accumulate
static __device__ __forceinline__ void mma_bf16(float* d, const uint32_t* a,
                                                const uint32_t* b) {
    asm volatile(
        "mma.sync.aligned.m16n8k16.row.col.f32.bf16.bf16.f32 "
        "{%0,%1,%2,%3}, {%4,%5,%6,%7}, {%8,%9}, {%0,%1,%2,%3};"
        : "+f"(d[0]), "+f"(d[1]), "+f"(d[2]), "+f"(d[3])
        : "r"(a[0]), "r"(a[1]), "r"(a[2]), "r"(a[3]), "r"(b[0]), "r"(b[1]));
}

// Split two fp32 into packed bf16 (hi) and packed bf16 residual (lo).
// Low 16 bits hold the first (lower-k) element.
static __device__ __forceinline__ void split2(float x0, float x1,
                                              uint32_t& hi, uint32_t& lo) {
    __nv_bfloat16 h0 = __float2bfloat16(x0);
    __nv_bfloat16 h1 = __float2bfloat16(x1);
    __nv_bfloat16 l0 = __float2bfloat16(x0 - __bfloat162float(h0));
    __nv_bfloat16 l1 = __float2bfloat16(x1 - __bfloat162float(h1));
    hi = (uint32_t)__bfloat16_as_ushort(h0) | ((uint32_t)__bfloat16_as_ushort(h1) << 16);
    lo = (uint32_t)__bfloat16_as_ushort(l0) | ((uint32_t)__bfloat16_as_ushort(l1) << 16);
}

// ---------------------------------------------------------------------------
// bf16-split mma.sync GEMM: D[128,128] = A[128x1024] @ W[1024,ldb][col0:+128]
// 256 threads, 8 warps (2 M x 4 N), warp tile 64x32, BK=32, double buffered.
// Smem per buffer: A_hi/A_lo [128 rows][40 bf16], B_hi/B_lo [128 n][40 bf16].
// mode 0: QKV epilogue (route q/k/v, scale q), A = x (host pointer).
// mode 1: plain out + bias, A resolved DEVICE-SIDE to g_att (host passes null).
// ---------------------------------------------------------------------------
static constexpr int PITCH = 40;             // bf16 per row (conflict-free frag loads)
static constexpr int MAT   = 128 * PITCH;    // 5120 bf16 per matrix
static constexpr int BUF   = 4 * MAT;        // A_hi, A_lo, B_hi, B_lo
static constexpr int GEMM_SMEM = 2 * BUF * 2;  // 81920 bytes

__global__ __launch_bounds__(256) void mma_gemm(
    const float* __restrict__ Ain,   // mode0: x [M1,1024]; mode1: ignored (null)
    const float* __restrict__ W,     // [1024, ldb] row-major
    const float* __restrict__ bias,  // [ldb]
    float* __restrict__ out0,        // mode1 dst
    float* __restrict__ kout,
    float* __restrict__ vout,
    int ldb, int mode)
{
    extern __shared__ __nv_bfloat16 smb[];

    // CRITICAL: __device__ globals must be referenced from device code, not
    // passed as host-side kernel arguments.
    const float* A = (mode == 1) ? g_att : Ain;

    const int tid  = threadIdx.x;
    const int wid  = tid >> 5;
    const int lane = tid & 31;
    const int g    = lane >> 2;   // group id (0..7)
    const int tig  = lane & 3;    // thread in group
    const int wm   = wid >> 2;    // 0..1
    const int wn   = wid & 3;     // 0..3
    const int row0 = blockIdx.y * 128;
    const int col0 = blockIdx.x * 128;

    float acc[4][4][4] = {};      // [mtile][ntile][frag]

    auto load_chunk = [&](int kc, int bf) {
        __nv_bfloat16* Ah = smb + bf * BUF;
        __nv_bfloat16* Al = Ah + MAT;
        __nv_bfloat16* Bh = Ah + 2 * MAT;
        __nv_bfloat16* Bl = Ah + 3 * MAT;

        // A: 128 rows x 32 k (k-contiguous in both gmem and smem)
        const float* Ab = A + (size_t)row0 * 1024 + kc * 32;
        #pragma unroll
        for (int q = 0; q < 4; q++) {
            int idx = q * 256 + tid;
            int m  = idx >> 3;
            int k4 = (idx & 7) * 4;
            float4 v = *reinterpret_cast<const float4*>(Ab + (size_t)m * 1024 + k4);
            uint32_t h0, l0, h1, l1;
            split2(v.x, v.y, h0, l0);
            split2(v.z, v.w, h1, l1);
            uint32_t* dh = reinterpret_cast<uint32_t*>(Ah + m * PITCH + k4);
            dh[0] = h0; dh[1] = h1;
            uint32_t* dl = reinterpret_cast<uint32_t*>(Al + m * PITCH + k4);
            dl[0] = l0; dl[1] = l1;
        }

        // B: transpose W[k][n] -> smem[n][k]. Thread handles a k-pair x 4 n.
        const float* Wb = W + (size_t)(kc * 32) * ldb + col0;
        #pragma unroll
        for (int q = 0; q < 2; q++) {
            int idx = q * 256 + tid;      // 0..511
            int kp  = idx >> 5;           // 0..15 k-pair
            int n4  = (idx & 31) * 4;
            float4 r0 = *reinterpret_cast<const float4*>(Wb + (size_t)(2 * kp) * ldb + n4);
            float4 r1 = *reinterpret_cast<const float4*>(Wb + (size_t)(2 * kp + 1) * ldb + n4);
            float e0[4] = {r0.x, r0.y, r0.z, r0.w};
            float e1[4] = {r1.x, r1.y, r1.z, r1.w};
            #pragma unroll
            for (int j = 0; j < 4; j++) {
                uint32_t h, l;
                split2(e0[j], e1[j], h, l);
                *reinterpret_cast<uint32_t*>(Bh + (n4 + j) * PITCH + 2 * kp) = h;
                *reinterpret_cast<uint32_t*>(Bl + (n4 + j) * PITCH + 2 * kp) = l;
            }
        }
    };

    load_chunk(0, 0);
    __syncthreads();

    for (int kc = 0; kc < 32; kc++) {
        const int bf = kc & 1;
        if (kc + 1 < 32) load_chunk(kc + 1, bf ^ 1);

        const __nv_bfloat16* Ah = smb + bf * BUF;
        const __nv_bfloat16* Al = Ah + MAT;
        const __nv_bfloat16* Bh = Ah + 2 * MAT;
        const __nv_bfloat16* Bl = Ah + 3 * MAT;

        #pragma unroll
        for (int s = 0; s < 2; s++) {          // two k16 slabs per chunk
            const int ko = s * 16 + 2 * tig;
            uint32_t ah[4][4], al[4][4];
            #pragma unroll
            for (int mt = 0; mt < 4; mt++) {
                int r = wm * 64 + mt * 16 + g;
                ah[mt][0] = *reinterpret_cast<const uint32_t*>(Ah + r * PITCH + ko);
                ah[mt][1] = *reinterpret_cast<const uint32_t*>(Ah + (r + 8) * PITCH + ko);
                ah[mt][2] = *reinterpret_cast<const uint32_t*>(Ah + r * PITCH + ko + 8);
                ah[mt][3] = *reinterpret_cast<const uint32_t*>(Ah + (r + 8) * PITCH + ko + 8);
                al[mt][0] = *reinterpret_cast<const uint32_t*>(Al + r * PITCH + ko);
                al[mt][1] = *reinterpret_cast<const uint32_t*>(Al + (r + 8) * PITCH + ko);
                al[mt][2] = *reinterpret_cast<const uint32_t*>(Al + r * PITCH + ko + 8);
                al[mt][3] = *reinterpret_cast<const uint32_t*>(Al + (r + 8) * PITCH + ko + 8);
            }
            uint32_t bh[4][2], bl[4][2];
            #pragma unroll
            for (int nt = 0; nt < 4; nt++) {
                int cn = wn * 32 + nt * 8 + g;
                bh[nt][0] = *reinterpret_cast<const uint32_t*>(Bh + cn * PITCH + ko);
                bh[nt][1] = *reinterpret_cast<const uint32_t*>(Bh + cn * PITCH + ko + 8);
                bl[nt][0] = *reinterpret_cast<const uint32_t*>(Bl + cn * PITCH + ko);
                bl[nt][1] = *reinterpret_cast<const uint32_t*>(Bl + cn * PITCH + ko + 8);
            }
            #pragma unroll
            for (int mt = 0; mt < 4; mt++)
                #pragma unroll
                for (int nt = 0; nt < 4; nt++) {
                    mma_bf16(acc[mt][nt], ah[mt], bh[nt]);
                    mma_bf16(acc[mt][nt], ah[mt], bl[nt]);
                    mma_bf16(acc[mt][nt], al[mt], bh[nt]);
                }
        }
        __syncthreads();
    }

    // Epilogue. Thread owns rows {g, g+8} per mt, cols {2tig, 2tig+1} per nt.
    #pragma unroll
    for (int mt = 0; mt < 4; mt++) {
        #pragma unroll
        for (int half = 0; half < 2; half++) {
            const int m  = row0 + wm * 64 + mt * 16 + g + half * 8;
            const int b_ = m >> 11;
            const int t_ = m & 2047;
            #pragma unroll
            for (int nt = 0; nt < 4; nt++) {
                const int n = col0 + wn * 32 + nt * 8 + 2 * tig;
                float v0 = acc[mt][nt][half * 2 + 0] + bias[n];
                float v1 = acc[mt][nt][half * 2 + 1] + bias[n + 1];
                if (mode == 1) {
                    float2 o = make_float2(v0, v1);
                    *reinterpret_cast<float2*>(out0 + (size_t)m * 1024 + n) = o;
                } else {
                    const int region = n >> 10;
                    const int nn = n & 1023;
                    const int h  = nn >> 6;
                    const int d0 = nn & 63;
                    float* dstp = (region == 0) ? g_q : ((region == 1) ? kout : vout);
                    const float sc = (region == 0) ? 0.125f : 1.0f;
                    float2 o = make_float2(v0 * sc, v1 * sc);
                    *reinterpret_cast<float2*>(
                        dstp + (((size_t)(b_ * H + h) * T + t_) * HD + d0)) = o;
                }
            }
        }
    }
}

// ---------------------------------------------------------------------------
// Flash attention — byte-identical to the R3 passing version.
// ---------------------------------------------------------------------------
__global__ __launch_bounds__(256) void attn_kernel(
    const float* __restrict__ kbuf,
    const float* __restrict__ vbuf)
{
    extern __shared__ float sm[];
    float* Qs = sm;
    float* Ks = Qs + 64 * 68;
    float* Vs = Ks + 64 * 68;
    float* Ps = Vs + 64 * 68;

    const int qi  = blockIdx.x;
    const int bh  = blockIdx.y;
    const int tid = threadIdx.x;
    const int tx  = tid & 15;
    const int ty  = tid >> 4;

    const float* qptr = g_q  + ((long)bh * T + (long)qi * 64) * HD;
    const float* kptr = kbuf + (long)bh * T * HD;
    const float* vptr = vbuf + (long)bh * T * HD;

    for (int i = tid; i < 64 * 16; i += 256) {
        int r = i >> 4, d4 = (i & 15) * 4;
        float4 q = *reinterpret_cast<const float4*>(qptr + r * HD + d4);
        Qs[(d4 + 0) * 68 + r] = q.x; Qs[(d4 + 1) * 68 + r] = q.y;
        Qs[(d4 + 2) * 68 + r] = q.z; Qs[(d4 + 3) * 68 + r] = q.w;
    }

    float acc[4][4] = {};
    float mrow[4], lrow[4];
    #pragma unroll
    for (int i = 0; i < 4; i++) { mrow[i] = -1e30f; lrow[i] = 0.f; }

    for (int kb = 0; kb <= qi; kb++) {
        __syncthreads();
        for (int i = tid; i < 64 * 16; i += 256) {
            int r = i >> 4, d4 = (i & 15) * 4;
            float4 k = *reinterpret_cast<const float4*>(kptr + (kb * 64 + r) * HD + d4);
            Ks[(d4 + 0) * 68 + r] = k.x; Ks[(d4 + 1) * 68 + r] = k.y;
            Ks[(d4 + 2) * 68 + r] = k.z; Ks[(d4 + 3) * 68 + r] = k.w;
            float4 v = *reinterpret_cast<const float4*>(vptr + (kb * 64 + r) * HD + d4);
            *reinterpret_cast<float4*>(Vs + r * 68 + d4) = v;
        }
        __syncthreads();

        float s[4][4] = {};
        #pragma unroll 8
        for (int d = 0; d < 64; d++) {
            float4 a = *reinterpret_cast<const float4*>(Qs + d * 68 + ty * 4);
            float4 b = *reinterpret_cast<const float4*>(Ks + d * 68 + tx * 4);
            float av[4] = {a.x, a.y, a.z, a.w};
            float bv[4] = {b.x, b.y, b.z, b.w};
            #pragma unroll
            for (int i = 0; i < 4; i++)
                #pragma unroll
                for (int j = 0; j < 4; j++)
                    s[i][j] = fmaf(av[i], bv[j], s[i][j]);
        }

        if (kb == qi) {
            #pragma unroll
            for (int i = 0; i < 4; i++)
                #pragma unroll
                for (int j = 0; j < 4; j++)
                    if (tx * 4 + j > ty * 4 + i) s[i][j] = -1e30f;
        }

        #pragma unroll
        for (int i = 0; i < 4; i++) {
            float tmax = fmaxf(fmaxf(s[i][0], s[i][1]), fmaxf(s[i][2], s[i][3]));
            tmax = fmaxf(tmax, __shfl_xor_sync(0xffffffffu, tmax, 1));
            tmax = fmaxf(tmax, __shfl_xor_sync(0xffffffffu, tmax, 2));
            tmax = fmaxf(tmax, __shfl_xor_sync(0xffffffffu, tmax, 4));
            tmax = fmaxf(tmax, __shfl_xor_sync(0xffffffffu, tmax, 8));
            float mnew = fmaxf(mrow[i], tmax);
            float corr = __expf(mrow[i] - mnew);
            lrow[i] *= corr;
            #pragma unroll
            for (int j = 0; j < 4; j++) acc[i][j] *= corr;
            float ps = 0.f;
            #pragma unroll
            for (int j = 0; j < 4; j++) {
                float p = __expf(s[i][j] - mnew);
                ps += p;
                Ps[(tx * 4 + j) * 68 + (ty * 4 + i)] = p;
            }
            ps += __shfl_xor_sync(0xffffffffu, ps, 1);
            ps += __shfl_xor_sync(0xffffffffu, ps, 2);
            ps += __shfl_xor_sync(0xffffffffu, ps, 4);
            ps += __shfl_xor_sync(0xffffffffu, ps, 8);
            lrow[i] += ps;
            mrow[i] = mnew;
        }
        __syncthreads();

        #pragma unroll 8
        for (int k = 0; k < 64; k++) {
            float4 p = *reinterpret_cast<const float4*>(Ps + k * 68 + ty * 4);
            float4 v = *reinterpret_cast<const float4*>(Vs + k * 68 + tx * 4);
            float pv[4] = {p.x, p.y, p.z, p.w};
            float vv[4] = {v.x, v.y, v.z, v.w};
            #pragma unroll
            for (int i = 0; i < 4; i++)
                #pragma unroll
                for (int j = 0; j < 4; j++)
                    acc[i][j] = fmaf(pv[i], vv[j], acc[i][j]);
        }
    }

    const int b_ = bh >> 4;
    const int h_ = bh & 15;
    #pragma unroll
    for (int i = 0; i < 4; i++) {
        int qg = qi * 64 + ty * 4 + i;
        float inv = 1.f / lrow[i];
        float4 o;
        o.x = acc[i][0] * inv; o.y = acc[i][1] * inv;
        o.z = acc[i][2] * inv; o.w = acc[i][3] * inv;
        *reinterpret_cast<float4*>(g_att + ((long)(b_ * T + qg)) * C + h_ * 64 + tx * 4) = o;
    }
}

// ---------------------------------------------------------------------------
extern "C" void kernel_launch(void* const* d_in, const int* in_sizes, int n_in,
                              void* d_out, int out_size)
{
    const float* x    = (const float*)d_in[0];
    const float* Wqkv = (const float*)d_in[1];
    const float* bqkv = (const float*)d_in[2];
    const float* Wout = (const float*)d_in[3];
    const float* bout = (const float*)d_in[4];

    float* out  = (float*)d_out;
    float* kout = out + BTC;
    float* vout = out + 2 * BTC;

    cudaFuncSetAttribute(mma_gemm, cudaFuncAttributeMaxDynamicSharedMemorySize,
                         GEMM_SMEM);

    // 1) QKV projection (bf16-split mma.sync)
    mma_gemm<<<dim3(N1 / 128, M1 / 128), 256, GEMM_SMEM>>>(
        x, Wqkv, bqkv, nullptr, kout, vout, N1, 0);

    // 2) causal flash attention (fp32 SIMT)
    const size_t smem = (size_t)(4 * 64 * 68) * sizeof(float);
    cudaFuncSetAttribute(attn_kernel,
                         cudaFuncAttributeMaxDynamicSharedMemorySize, (int)smem);
    attn_kernel<<<dim3(T / 64, B * H), 256, smem>>>(kout, vout);

    // 3) output projection (bf16-split mma.sync; A resolved to g_att in-kernel)
    mma_gemm<<<dim3(C / 128, M1 / 128), 256, GEMM_SMEM>>>(
        nullptr, Wout, bout, out, nullptr, nullptr, C, 1);
}

// round 15
// speedup vs baseline: 1.7925x; 1.7925x over previous
#include <cuda_runtime.h>
#include <cuda_bf16.h>
#include <cstdint>

// Problem constants
static constexpr int B  = 4;
static constexpr int T  = 2048;
static constexpr int C  = 1024;
static constexpr int H  = 16;
static constexpr int HD = 64;
static constexpr int M1  = B * T;      // 8192
static constexpr int N1  = 3 * C;      // 3072
static constexpr int BTC = B * T * C;  // 8388608

// Scratch (device globals; NEVER passed as host-side kernel args)
__device__ float g_q[BTC];             // q in [B,H,T,HD], pre-scaled by 1/8
// Tiled bf16 operands (uint4 units). Layout: [tile128][chunk32][seg s][loc128]
// uint4 idx = ((tile*32 + c)*4 + s)*128 + loc ; uint4 = 8 bf16 of k seg s*8..+7
__device__ uint4 g_xt[2][1048576];     // x  hi/lo   (64 m-tiles)
__device__ uint4 g_at[2][1048576];     // attn out hi/lo (64 m-tiles)
__device__ uint4 g_wt[2][524288];      // W^T hi/lo: Wqkv tiles 0..23, Wout 24..31

static __device__ __forceinline__ void split2(float x0, float x1,
                                              uint32_t& hi, uint32_t& lo) {
    __nv_bfloat16 h0 = __float2bfloat16(x0);
    __nv_bfloat16 h1 = __float2bfloat16(x1);
    __nv_bfloat16 l0 = __float2bfloat16(x0 - __bfloat162float(h0));
    __nv_bfloat16 l1 = __float2bfloat16(x1 - __bfloat162float(h1));
    hi = (uint32_t)__bfloat16_as_ushort(h0) | ((uint32_t)__bfloat16_as_ushort(h1) << 16);
    lo = (uint32_t)__bfloat16_as_ushort(l0) | ((uint32_t)__bfloat16_as_ushort(l1) << 16);
}

static __device__ __forceinline__ void mma_bf16(float* d, const uint32_t* a,
                                                const uint32_t* b) {
    asm volatile(
        "mma.sync.aligned.m16n8k16.row.col.f32.bf16.bf16.f32 "
        "{%0,%1,%2,%3}, {%4,%5,%6,%7}, {%8,%9}, {%0,%1,%2,%3};"
        : "+f"(d[0]), "+f"(d[1]), "+f"(d[2]), "+f"(d[3])
        : "r"(a[0]), "r"(a[1]), "r"(a[2]), "r"(a[3]), "r"(b[0]), "r"(b[1]));
}

static __device__ __forceinline__ uint32_t smem_u32(const void* p) {
    uint32_t a;
    asm("{ .reg .u64 t; cvta.to.shared.u64 t, %1; cvt.u32.u64 %0, t; }"
        : "=r"(a) : "l"(p));
    return a;
}
static __device__ __forceinline__ void cp16(uint32_t dst, const void* src) {
    asm volatile("cp.async.cg.shared.global [%0], [%1], 16;" :: "r"(dst), "l"(src));
}
#define CP_COMMIT() asm volatile("cp.async.commit_group;" ::: "memory")
#define CP_WAIT0()  asm volatile("cp.async.wait_group 0;" ::: "memory")
#define LDSM_X4(r0, r1, r2, r3, addr) \
    asm volatile("ldmatrix.sync.aligned.m8n8.x4.shared.b16 {%0,%1,%2,%3}, [%4];" \
                 : "=r"(r0), "=r"(r1), "=r"(r2), "=r"(r3) : "r"(addr))

// ---------------------------------------------------------------------------
// Pre-pass: x [8192,1024] f32 -> tiled hi/lo bf16
// ---------------------------------------------------------------------------
__global__ __launch_bounds__(256) void convert_x_kernel(const float* __restrict__ x) {
    int gid = blockIdx.x * 256 + threadIdx.x;      // 2,097,152 threads
    int m  = gid >> 8;
    int k4 = (gid & 255) * 4;
    float4 v = *reinterpret_cast<const float4*>(x + (size_t)m * 1024 + k4);
    uint32_t h0, l0, h1, l1;
    split2(v.x, v.y, h0, l0);
    split2(v.z, v.w, h1, l1);
    int tile = m >> 7, mloc = m & 127;
    int c = k4 >> 5, kk = k4 & 31, s = kk >> 3, half = (kk >> 2) & 1;
    size_t u4 = ((size_t)(tile * 32 + c) * 4 + s) * 128 + mloc;
    *reinterpret_cast<uint2*>(reinterpret_cast<char*>(&g_xt[0][u4]) + half * 8) = make_uint2(h0, h1);
    *reinterpret_cast<uint2*>(reinterpret_cast<char*>(&g_xt[1][u4]) + half * 8) = make_uint2(l0, l1);
}

// ---------------------------------------------------------------------------
// Pre-pass: W [1024, ldb] f32 -> transposed [n][k] tiled hi/lo bf16
// ---------------------------------------------------------------------------
__global__ __launch_bounds__(256) void convert_w_kernel(const float* __restrict__ W,
                                                        int ldb, int tile_off) {
    __shared__ float tr[32][33];
    const int k0 = blockIdx.x * 32, n0 = blockIdx.y * 32;
    const int tid = threadIdx.x;
    const int r = tid >> 3, c4 = (tid & 7) * 4;
    float4 v = *reinterpret_cast<const float4*>(W + (size_t)(k0 + r) * ldb + n0 + c4);
    tr[c4 + 0][r] = v.x; tr[c4 + 1][r] = v.y;
    tr[c4 + 2][r] = v.z; tr[c4 + 3][r] = v.w;
    __syncthreads();
    // write n-row r, k segment c4..c4+3
    int n = n0 + r;
    int k = k0 + c4;
    uint32_t h0, l0, h1, l1;
    split2(tr[r][c4 + 0], tr[r][c4 + 1], h0, l0);
    split2(tr[r][c4 + 2], tr[r][c4 + 3], h1, l1);
    int tile = (n >> 7) + tile_off, nloc = n & 127;
    int c = k >> 5, kk = k & 31, s = kk >> 3, half = (kk >> 2) & 1;
    size_t u4 = ((size_t)(tile * 32 + c) * 4 + s) * 128 + nloc;
    *reinterpret_cast<uint2*>(reinterpret_cast<char*>(&g_wt[0][u4]) + half * 8) = make_uint2(h0, h1);
    *reinterpret_cast<uint2*>(reinterpret_cast<char*>(&g_wt[1][u4]) + half * 8) = make_uint2(l0, l1);
}

// ---------------------------------------------------------------------------
// bf16-split HMMA GEMM with cp.async + ldmatrix.
// D[128,128] per CTA, BK=32, 8 warps (2Mx4N), warp tile 64x32.
// Smem/buffer: Ah, Al, Bh, Bl each [128][40] bf16 (pitch 80B, conflict-free).
// mode 0: A = g_xt, W tiles 0..23, QKV routing epilogue.
// mode 1: A = g_at, W tiles 24..31, plain out + bias.
// ---------------------------------------------------------------------------
static constexpr int GEMM_SMEM = 81920;   // 2 buffers x 4 mats x 10240 B

__global__ __launch_bounds__(256, 2) void mma_gemm(
    const float* __restrict__ bias,
    float* __restrict__ out0,
    float* __restrict__ kout,
    float* __restrict__ vout,
    int mode)
{
    extern __shared__ char dsm[];
    const uint32_t sb = smem_u32(dsm);

    const uint4* __restrict__ Ah_g = mode ? g_at[0] : g_xt[0];
    const uint4* __restrict__ Al_g = mode ? g_at[1] : g_xt[1];
    const int woff = mode ? 24 : 0;

    const int tid  = threadIdx.x;
    const int wid  = tid >> 5;
    const int lane = tid & 31;
    const int g    = lane >> 2;
    const int tig  = lane & 3;
    const int wm   = wid >> 2;    // 0..1
    const int wn   = wid & 3;     // 0..3
    const int bx   = blockIdx.x;  // n tile
    const int by   = blockIdx.y;  // m tile

    float acc[4][4][4] = {};

    // cp.async copy of chunk kc into buffer bf (4 matrices x 512 uint4)
    auto issue_copy = [&](int kc, int bf) {
        uint32_t sbase = sb + bf * 40960;
        #pragma unroll
        for (int it = 0; it < 2; it++) {
            int idx = it * 256 + tid;
            int s = idx >> 7, loc = idx & 127;
            uint32_t soff = loc * 80 + s * 16;
            size_t aidx = ((size_t)(by * 32 + kc) * 4 + s) * 128 + loc;
            size_t bidx = ((size_t)((bx + woff) * 32 + kc) * 4 + s) * 128 + loc;
            cp16(sbase + soff,          Ah_g + aidx);
            cp16(sbase + 10240 + soff,  Al_g + aidx);
            cp16(sbase + 20480 + soff,  g_wt[0] + bidx);
            cp16(sbase + 30720 + soff,  g_wt[1] + bidx);
        }
    };

    // ldmatrix lane base offsets (pitch 80 B)
    const int lrow = lane & 7;
    const uint32_t offA = (uint32_t)(wm * 64 + lrow + ((lane >> 3) & 1) * 8) * 80
                          + ((lane >> 4) & 1) * 16;
    const uint32_t offB = (uint32_t)(wn * 32 + lrow + ((lane >> 4) & 1) * 8) * 80
                          + ((lane >> 3) & 1) * 16;

    issue_copy(0, 0);
    CP_COMMIT();
    CP_WAIT0();
    __syncthreads();

    for (int kc = 0; kc < 32; kc++) {
        const int bf = kc & 1;
        if (kc + 1 < 32) { issue_copy(kc + 1, bf ^ 1); CP_COMMIT(); }

        const uint32_t bufb = sb + bf * 40960;
        #pragma unroll
        for (int slab = 0; slab < 2; slab++) {
            const uint32_t ks = slab * 32;
            uint32_t bh[4][2], bl[4][2];
            #pragma unroll
            for (int p = 0; p < 2; p++) {
                LDSM_X4(bh[2*p][0], bh[2*p][1], bh[2*p+1][0], bh[2*p+1][1],
                        bufb + 20480 + offB + p * 1280 + ks);
                LDSM_X4(bl[2*p][0], bl[2*p][1], bl[2*p+1][0], bl[2*p+1][1],
                        bufb + 30720 + offB + p * 1280 + ks);
            }
            #pragma unroll
            for (int mt = 0; mt < 4; mt++) {
                uint32_t ah[4], al[4];
                LDSM_X4(ah[0], ah[1], ah[2], ah[3],
                        bufb + offA + mt * 1280 + ks);
                LDSM_X4(al[0], al[1], al[2], al[3],
                        bufb + 10240 + offA + mt * 1280 + ks);
                #pragma unroll
                for (int nt = 0; nt < 4; nt++) {
                    mma_bf16(acc[mt][nt], ah, bh[nt]);
                    mma_bf16(acc[mt][nt], ah, bl[nt]);
                    mma_bf16(acc[mt][nt], al, bh[nt]);
                }
            }
        }
        if (kc + 1 < 32) CP_WAIT0();
        __syncthreads();
    }

    // Epilogue (proven in R14). Thread owns rows {g, g+8}, cols {2tig, 2tig+1}.
    const int row0 = by * 128;
    const int col0 = bx * 128;
    #pragma unroll
    for (int mt = 0; mt < 4; mt++) {
        #pragma unroll
        for (int half = 0; half < 2; half++) {
            const int m  = row0 + wm * 64 + mt * 16 + g + half * 8;
            const int b_ = m >> 11;
            const int t_ = m & 2047;
            #pragma unroll
            for (int nt = 0; nt < 4; nt++) {
                const int n = col0 + wn * 32 + nt * 8 + 2 * tig;
                float v0 = acc[mt][nt][half * 2 + 0] + bias[n];
                float v1 = acc[mt][nt][half * 2 + 1] + bias[n + 1];
                if (mode == 1) {
                    *reinterpret_cast<float2*>(out0 + (size_t)m * 1024 + n) =
                        make_float2(v0, v1);
                } else {
                    const int region = n >> 10;
                    const int nn = n & 1023;
                    const int h  = nn >> 6;
                    const int d0 = nn & 63;
                    float* dstp = (region == 0) ? g_q : ((region == 1) ? kout : vout);
                    const float sc = (region == 0) ? 0.125f : 1.0f;
                    *reinterpret_cast<float2*>(
                        dstp + (((size_t)(b_ * H + h) * T + t_) * HD + d0)) =
                        make_float2(v0 * sc, v1 * sc);
                }
            }
        }
    }
}

// ---------------------------------------------------------------------------
// Flash attention — R3-proven body; epilogue writes tiled hi/lo bf16 to g_at.
// ---------------------------------------------------------------------------
__global__ __launch_bounds__(256) void attn_kernel(
    const float* __restrict__ kbuf,
    const float* __restrict__ vbuf)
{
    extern __shared__ float sm[];
    float* Qs = sm;
    float* Ks = Qs + 64 * 68;
    float* Vs = Ks + 64 * 68;
    float* Ps = Vs + 64 * 68;

    const int qi  = blockIdx.x;
    const int bh  = blockIdx.y;
    const int tid = threadIdx.x;
    const int tx  = tid & 15;
    const int ty  = tid >> 4;

    const float* qptr = g_q  + ((long)bh * T + (long)qi * 64) * HD;
    const float* kptr = kbuf + (long)bh * T * HD;
    const float* vptr = vbuf + (long)bh * T * HD;

    for (int i = tid; i < 64 * 16; i += 256) {
        int r = i >> 4, d4 = (i & 15) * 4;
        float4 q = *reinterpret_cast<const float4*>(qptr + r * HD + d4);
        Qs[(d4 + 0) * 68 + r] = q.x; Qs[(d4 + 1) * 68 + r] = q.y;
        Qs[(d4 + 2) * 68 + r] = q.z; Qs[(d4 + 3) * 68 + r] = q.w;
    }

    float acc[4][4] = {};
    float mrow[4], lrow[4];
    #pragma unroll
    for (int i = 0; i < 4; i++) { mrow[i] = -1e30f; lrow[i] = 0.f; }

    for (int kb = 0; kb <= qi; kb++) {
        __syncthreads();
        for (int i = tid; i < 64 * 16; i += 256) {
            int r = i >> 4, d4 = (i & 15) * 4;
            float4 k = *reinterpret_cast<const float4*>(kptr + (kb * 64 + r) * HD + d4);
            Ks[(d4 + 0) * 68 + r] = k.x; Ks[(d4 + 1) * 68 + r] = k.y;
            Ks[(d4 + 2) * 68 + r] = k.z; Ks[(d4 + 3) * 68 + r] = k.w;
            float4 v = *reinterpret_cast<const float4*>(vptr + (kb * 64 + r) * HD + d4);
            *reinterpret_cast<float4*>(Vs + r * 68 + d4) = v;
        }
        __syncthreads();

        float s[4][4] = {};
        #pragma unroll 8
        for (int d = 0; d < 64; d++) {
            float4 a = *reinterpret_cast<const float4*>(Qs + d * 68 + ty * 4);
            float4 b = *reinterpret_cast<const float4*>(Ks + d * 68 + tx * 4);
            float av[4] = {a.x, a.y, a.z, a.w};
            float bv[4] = {b.x, b.y, b.z, b.w};
            #pragma unroll
            for (int i = 0; i < 4; i++)
                #pragma unroll
                for (int j = 0; j < 4; j++)
                    s[i][j] = fmaf(av[i], bv[j], s[i][j]);
        }

        if (kb == qi) {
            #pragma unroll
            for (int i = 0; i < 4; i++)
                #pragma unroll
                for (int j = 0; j < 4; j++)
                    if (tx * 4 + j > ty * 4 + i) s[i][j] = -1e30f;
        }

        #pragma unroll
        for (int i = 0; i < 4; i++) {
            float tmax = fmaxf(fmaxf(s[i][0], s[i][1]), fmaxf(s[i][2], s[i][3]));
            tmax = fmaxf(tmax, __shfl_xor_sync(0xffffffffu, tmax, 1));
            tmax = fmaxf(tmax, __shfl_xor_sync(0xffffffffu, tmax, 2));
            tmax = fmaxf(tmax, __shfl_xor_sync(0xffffffffu, tmax, 4));
            tmax = fmaxf(tmax, __shfl_xor_sync(0xffffffffu, tmax, 8));
            float mnew = fmaxf(mrow[i], tmax);
            float corr = __expf(mrow[i] - mnew);
            lrow[i] *= corr;
            #pragma unroll
            for (int j = 0; j < 4; j++) acc[i][j] *= corr;
            float ps = 0.f;
            #pragma unroll
            for (int j = 0; j < 4; j++) {
                float p = __expf(s[i][j] - mnew);
                ps += p;
                Ps[(tx * 4 + j) * 68 + (ty * 4 + i)] = p;
            }
            ps += __shfl_xor_sync(0xffffffffu, ps, 1);
            ps += __shfl_xor_sync(0xffffffffu, ps, 2);
            ps += __shfl_xor_sync(0xffffffffu, ps, 4);
            ps += __shfl_xor_sync(0xffffffffu, ps, 8);
            lrow[i] += ps;
            mrow[i] = mnew;
        }
        __syncthreads();

        #pragma unroll 8
        for (int k = 0; k < 64; k++) {
            float4 p = *reinterpret_cast<const float4*>(Ps + k * 68 + ty * 4);
            float4 v = *reinterpret_cast<const float4*>(Vs + k * 68 + tx * 4);
            float pv[4] = {p.x, p.y, p.z, p.w};
            float vv[4] = {v.x, v.y, v.z, v.w};
            #pragma unroll
            for (int i = 0; i < 4; i++)
                #pragma unroll
                for (int j = 0; j < 4; j++)
                    acc[i][j] = fmaf(pv[i], vv[j], acc[i][j]);
        }
    }

    // Epilogue: write tiled hi/lo bf16 into g_at (proj GEMM A operand)
    const int b_ = bh >> 4;
    const int h_ = bh & 15;
    const int k = h_ * 64 + tx * 4;
    const int c = k >> 5, kk = k & 31, s_ = kk >> 3, half = (kk >> 2) & 1;
    #pragma unroll
    for (int i = 0; i < 4; i++) {
        int qg = qi * 64 + ty * 4 + i;
        float inv = 1.f / lrow[i];
        float o0 = acc[i][0] * inv, o1 = acc[i][1] * inv;
        float o2 = acc[i][2] * inv, o3 = acc[i][3] * inv;
        int m = b_ * 2048 + qg;
        int tile = m >> 7, mloc = m & 127;
        size_t u4 = ((size_t)(tile * 32 + c) * 4 + s_) * 128 + mloc;
        uint32_t h0, l0, h1, l1;
        split2(o0, o1, h0, l0);
        split2(o2, o3, h1, l1);
        *reinterpret_cast<uint2*>(reinterpret_cast<char*>(&g_at[0][u4]) + half * 8) = make_uint2(h0, h1);
        *reinterpret_cast<uint2*>(reinterpret_cast<char*>(&g_at[1][u4]) + half * 8) = make_uint2(l0, l1);
    }
}

// ---------------------------------------------------------------------------
extern "C" void kernel_launch(void* const* d_in, const int* in_sizes, int n_in,
                              void* d_out, int out_size)
{
    const float* x    = (const float*)d_in[0];
    const float* Wqkv = (const float*)d_in[1];
    const float* bqkv = (const float*)d_in[2];
    const float* Wout = (const float*)d_in[3];
    const float* bout = (const float*)d_in[4];

    float* out  = (float*)d_out;
    float* kout = out + BTC;
    float* vout = out + 2 * BTC;

    // Pre-pass conversions (memory-bound, ~40us)
    convert_x_kernel<<<8192, 256>>>(x);
    convert_w_kernel<<<dim3(32, 96), 256>>>(Wqkv, N1, 0);
    convert_w_kernel<<<dim3(32, 32), 256>>>(Wout, C, 24);

    cudaFuncSetAttribute(mma_gemm, cudaFuncAttributeMaxDynamicSharedMemorySize,
                         GEMM_SMEM);

    // 1) QKV projection
    mma_gemm<<<dim3(N1 / 128, M1 / 128), 256, GEMM_SMEM>>>(
        bqkv, nullptr, kout, vout, 0);

    // 2) causal flash attention
    const size_t smem = (size_t)(4 * 64 * 68) * sizeof(float);
    cudaFuncSetAttribute(attn_kernel,
                         cudaFuncAttributeMaxDynamicSharedMemorySize, (int)smem);
    attn_kernel<<<dim3(T / 64, B * H), 256, smem>>>(kout, vout);

    // 3) output projection
    mma_gemm<<<dim3(C / 128, M1 / 128), 256, GEMM_SMEM>>>(
        bout, out, nullptr, nullptr, 1);
}

// round 16
// speedup vs baseline: 3.0159x; 1.6826x over previous
#include <cuda_runtime.h>
#include <cuda_bf16.h>
#include <cstdint>

// Problem constants
static constexpr int B  = 4;
static constexpr int T  = 2048;
static constexpr int C  = 1024;
static constexpr int H  = 16;
static constexpr int HD = 64;
static constexpr int M1  = B * T;      // 8192
static constexpr int N1  = 3 * C;      // 3072
static constexpr int BTC = B * T * C;  // 8388608

// Scratch (device globals; NEVER passed as host-side kernel args)
// Tiled bf16 operands for GEMMs (uint4 units): idx = ((tile*32+c)*4+s)*128+loc
__device__ uint4 g_xt[2][1048576];     // x  hi/lo (64 m-tiles)
__device__ uint4 g_at[2][1048576];     // attn out hi/lo (64 m-tiles)
__device__ uint4 g_wt[2][524288];      // W^T hi/lo: Wqkv tiles 0..23, Wout 24..31
// Attention operands, natural [bh][t][hd] rows, bf16 hi/lo (uint4 for alignment)
__device__ uint4 g_qbu[2][1048576];    // q, pre-scaled by 0.125
__device__ uint4 g_kbu[2][1048576];
__device__ uint4 g_vbu[2][1048576];

static __device__ __forceinline__ void split2(float x0, float x1,
                                              uint32_t& hi, uint32_t& lo) {
    __nv_bfloat16 h0 = __float2bfloat16(x0);
    __nv_bfloat16 h1 = __float2bfloat16(x1);
    __nv_bfloat16 l0 = __float2bfloat16(x0 - __bfloat162float(h0));
    __nv_bfloat16 l1 = __float2bfloat16(x1 - __bfloat162float(h1));
    hi = (uint32_t)__bfloat16_as_ushort(h0) | ((uint32_t)__bfloat16_as_ushort(h1) << 16);
    lo = (uint32_t)__bfloat16_as_ushort(l0) | ((uint32_t)__bfloat16_as_ushort(l1) << 16);
}

static __device__ __forceinline__ void mma_bf16(float* d, const uint32_t* a,
                                                const uint32_t* b) {
    asm volatile(
        "mma.sync.aligned.m16n8k16.row.col.f32.bf16.bf16.f32 "
        "{%0,%1,%2,%3}, {%4,%5,%6,%7}, {%8,%9}, {%0,%1,%2,%3};"
        : "+f"(d[0]), "+f"(d[1]), "+f"(d[2]), "+f"(d[3])
        : "r"(a[0]), "r"(a[1]), "r"(a[2]), "r"(a[3]), "r"(b[0]), "r"(b[1]));
}

static __device__ __forceinline__ uint32_t smem_u32(const void* p) {
    uint32_t a;
    asm("{ .reg .u64 t; cvta.to.shared.u64 t, %1; cvt.u32.u64 %0, t; }"
        : "=r"(a) : "l"(p));
    return a;
}
static __device__ __forceinline__ void cp16(uint32_t dst, const void* src) {
    asm volatile("cp.async.cg.shared.global [%0], [%1], 16;" :: "r"(dst), "l"(src));
}
#define CP_COMMIT() asm volatile("cp.async.commit_group;" ::: "memory")
#define CP_WAIT0()  asm volatile("cp.async.wait_group 0;" ::: "memory")
#define LDSM_X4(r0, r1, r2, r3, addr) \
    asm volatile("ldmatrix.sync.aligned.m8n8.x4.shared.b16 {%0,%1,%2,%3}, [%4];" \
                 : "=r"(r0), "=r"(r1), "=r"(r2), "=r"(r3) : "r"(addr))
#define LDSM_X4_T(r0, r1, r2, r3, addr) \
    asm volatile("ldmatrix.sync.aligned.m8n8.x4.trans.shared.b16 {%0,%1,%2,%3}, [%4];" \
                 : "=r"(r0), "=r"(r1), "=r"(r2), "=r"(r3) : "r"(addr))

// ---------------------------------------------------------------------------
// Pre-pass: x [8192,1024] f32 -> tiled hi/lo bf16
// ---------------------------------------------------------------------------
__global__ __launch_bounds__(256) void convert_x_kernel(const float* __restrict__ x) {
    int gid = blockIdx.x * 256 + threadIdx.x;
    int m  = gid >> 8;
    int k4 = (gid & 255) * 4;
    float4 v = *reinterpret_cast<const float4*>(x + (size_t)m * 1024 + k4);
    uint32_t h0, l0, h1, l1;
    split2(v.x, v.y, h0, l0);
    split2(v.z, v.w, h1, l1);
    int tile = m >> 7, mloc = m & 127;
    int c = k4 >> 5, kk = k4 & 31, s = kk >> 3, half = (kk >> 2) & 1;
    size_t u4 = ((size_t)(tile * 32 + c) * 4 + s) * 128 + mloc;
    *reinterpret_cast<uint2*>(reinterpret_cast<char*>(&g_xt[0][u4]) + half * 8) = make_uint2(h0, h1);
    *reinterpret_cast<uint2*>(reinterpret_cast<char*>(&g_xt[1][u4]) + half * 8) = make_uint2(l0, l1);
}

// ---------------------------------------------------------------------------
// Pre-pass: W [1024, ldb] f32 -> transposed [n][k] tiled hi/lo bf16
// ---------------------------------------------------------------------------
__global__ __launch_bounds__(256) void convert_w_kernel(const float* __restrict__ W,
                                                        int ldb, int tile_off) {
    __shared__ float tr[32][33];
    const int k0 = blockIdx.x * 32, n0 = blockIdx.y * 32;
    const int tid = threadIdx.x;
    const int r = tid >> 3, c4 = (tid & 7) * 4;
    float4 v = *reinterpret_cast<const float4*>(W + (size_t)(k0 + r) * ldb + n0 + c4);
    tr[c4 + 0][r] = v.x; tr[c4 + 1][r] = v.y;
    tr[c4 + 2][r] = v.z; tr[c4 + 3][r] = v.w;
    __syncthreads();
    int n = n0 + r;
    int k = k0 + c4;
    uint32_t h0, l0, h1, l1;
    split2(tr[r][c4 + 0], tr[r][c4 + 1], h0, l0);
    split2(tr[r][c4 + 2], tr[r][c4 + 3], h1, l1);
    int tile = (n >> 7) + tile_off, nloc = n & 127;
    int c = k >> 5, kk = k & 31, s = kk >> 3, half = (kk >> 2) & 1;
    size_t u4 = ((size_t)(tile * 32 + c) * 4 + s) * 128 + nloc;
    *reinterpret_cast<uint2*>(reinterpret_cast<char*>(&g_wt[0][u4]) + half * 8) = make_uint2(h0, h1);
    *reinterpret_cast<uint2*>(reinterpret_cast<char*>(&g_wt[1][u4]) + half * 8) = make_uint2(l0, l1);
}

// ---------------------------------------------------------------------------
// bf16-split HMMA GEMM (proven R15). mode 0: QKV (+ bf16 scratch for attn).
// mode 1: proj.
// ---------------------------------------------------------------------------
static constexpr int GEMM_SMEM = 81920;

__global__ __launch_bounds__(256, 2) void mma_gemm(
    const float* __restrict__ bias,
    float* __restrict__ out0,
    float* __restrict__ kout,
    float* __restrict__ vout,
    int mode)
{
    extern __shared__ char dsm[];
    const uint32_t sb = smem_u32(dsm);

    const uint4* __restrict__ Ah_g = mode ? g_at[0] : g_xt[0];
    const uint4* __restrict__ Al_g = mode ? g_at[1] : g_xt[1];
    const int woff = mode ? 24 : 0;

    const int tid  = threadIdx.x;
    const int wid  = tid >> 5;
    const int lane = tid & 31;
    const int g    = lane >> 2;
    const int tig  = lane & 3;
    const int wm   = wid >> 2;
    const int wn   = wid & 3;
    const int bx   = blockIdx.x;
    const int by   = blockIdx.y;

    float acc[4][4][4] = {};

    auto issue_copy = [&](int kc, int bf) {
        uint32_t sbase = sb + bf * 40960;
        #pragma unroll
        for (int it = 0; it < 2; it++) {
            int idx = it * 256 + tid;
            int s = idx >> 7, loc = idx & 127;
            uint32_t soff = loc * 80 + s * 16;
            size_t aidx = ((size_t)(by * 32 + kc) * 4 + s) * 128 + loc;
            size_t bidx = ((size_t)((bx + woff) * 32 + kc) * 4 + s) * 128 + loc;
            cp16(sbase + soff,          Ah_g + aidx);
            cp16(sbase + 10240 + soff,  Al_g + aidx);
            cp16(sbase + 20480 + soff,  g_wt[0] + bidx);
            cp16(sbase + 30720 + soff,  g_wt[1] + bidx);
        }
    };

    const int lrow = lane & 7;
    const uint32_t offA = (uint32_t)(wm * 64 + lrow + ((lane >> 3) & 1) * 8) * 80
                          + ((lane >> 4) & 1) * 16;
    const uint32_t offB = (uint32_t)(wn * 32 + lrow + ((lane >> 4) & 1) * 8) * 80
                          + ((lane >> 3) & 1) * 16;

    issue_copy(0, 0);
    CP_COMMIT();
    CP_WAIT0();
    __syncthreads();

    for (int kc = 0; kc < 32; kc++) {
        const int bf = kc & 1;
        if (kc + 1 < 32) { issue_copy(kc + 1, bf ^ 1); CP_COMMIT(); }

        const uint32_t bufb = sb + bf * 40960;
        #pragma unroll
        for (int slab = 0; slab < 2; slab++) {
            const uint32_t ks = slab * 32;
            uint32_t bh[4][2], bl[4][2];
            #pragma unroll
            for (int p = 0; p < 2; p++) {
                LDSM_X4(bh[2*p][0], bh[2*p][1], bh[2*p+1][0], bh[2*p+1][1],
                        bufb + 20480 + offB + p * 1280 + ks);
                LDSM_X4(bl[2*p][0], bl[2*p][1], bl[2*p+1][0], bl[2*p+1][1],
                        bufb + 30720 + offB + p * 1280 + ks);
            }
            #pragma unroll
            for (int mt = 0; mt < 4; mt++) {
                uint32_t ah[4], al[4];
                LDSM_X4(ah[0], ah[1], ah[2], ah[3],
                        bufb + offA + mt * 1280 + ks);
                LDSM_X4(al[0], al[1], al[2], al[3],
                        bufb + 10240 + offA + mt * 1280 + ks);
                #pragma unroll
                for (int nt = 0; nt < 4; nt++) {
                    mma_bf16(acc[mt][nt], ah, bh[nt]);
                    mma_bf16(acc[mt][nt], ah, bl[nt]);
                    mma_bf16(acc[mt][nt], al, bh[nt]);
                }
            }
        }
        if (kc + 1 < 32) CP_WAIT0();
        __syncthreads();
    }

    const int row0 = by * 128;
    const int col0 = bx * 128;
    #pragma unroll
    for (int mt = 0; mt < 4; mt++) {
        #pragma unroll
        for (int half = 0; half < 2; half++) {
            const int m  = row0 + wm * 64 + mt * 16 + g + half * 8;
            const int b_ = m >> 11;
            const int t_ = m & 2047;
            #pragma unroll
            for (int nt = 0; nt < 4; nt++) {
                const int n = col0 + wn * 32 + nt * 8 + 2 * tig;
                float v0 = acc[mt][nt][half * 2 + 0] + bias[n];
                float v1 = acc[mt][nt][half * 2 + 1] + bias[n + 1];
                if (mode == 1) {
                    *reinterpret_cast<float2*>(out0 + (size_t)m * 1024 + n) =
                        make_float2(v0, v1);
                } else {
                    const int region = n >> 10;
                    const int nn = n & 1023;
                    const int h  = nn >> 6;
                    const int d0 = nn & 63;
                    size_t fid = ((size_t)(b_ * H + h) * T + t_) * HD + d0;
                    uint32_t hi, lo;
                    if (region == 0) {
                        split2(v0 * 0.125f, v1 * 0.125f, hi, lo);
                        *reinterpret_cast<uint32_t*>(
                            reinterpret_cast<__nv_bfloat16*>(g_qbu[0]) + fid) = hi;
                        *reinterpret_cast<uint32_t*>(
                            reinterpret_cast<__nv_bfloat16*>(g_qbu[1]) + fid) = lo;
                    } else if (region == 1) {
                        *reinterpret_cast<float2*>(kout + fid) = make_float2(v0, v1);
                        split2(v0, v1, hi, lo);
                        *reinterpret_cast<uint32_t*>(
                            reinterpret_cast<__nv_bfloat16*>(g_kbu[0]) + fid) = hi;
                        *reinterpret_cast<uint32_t*>(
                            reinterpret_cast<__nv_bfloat16*>(g_kbu[1]) + fid) = lo;
                    } else {
                        *reinterpret_cast<float2*>(vout + fid) = make_float2(v0, v1);
                        split2(v0, v1, hi, lo);
                        *reinterpret_cast<uint32_t*>(
                            reinterpret_cast<__nv_bfloat16*>(g_vbu[0]) + fid) = hi;
                        *reinterpret_cast<uint32_t*>(
                            reinterpret_cast<__nv_bfloat16*>(g_vbu[1]) + fid) = lo;
                    }
                }
            }
        }
    }
}

// ---------------------------------------------------------------------------
// Tensor-core flash attention. CTA = 128 queries of one (b,h), 8 warps,
// warp = 16 query rows x 128-key tile. bf16 hi/lo 3-term MMAs for S and PV.
// Smem: Qh/Ql [128][72], Kh/Kl [128][72], Vh/Vl [128][72]  (pitch 144 B).
// ---------------------------------------------------------------------------
static constexpr int ATTN_SMEM = 110592;

__global__ __launch_bounds__(256) void attn_kernel() {
    extern __shared__ char attnsm[];
    const uint32_t sb = smem_u32(attnsm);
    const int qi = blockIdx.x, bh = blockIdx.y;
    const int tid = threadIdx.x, wid = tid >> 5, lane = tid & 31;
    const int g = lane >> 2, tig = lane & 3, lrow = lane & 7;

    const char* qs0 = (const char*)g_qbu[0];
    const char* qs1 = (const char*)g_qbu[1];
    const char* ks0 = (const char*)g_kbu[0];
    const char* ks1 = (const char*)g_kbu[1];
    const char* vs0 = (const char*)g_vbu[0];
    const char* vs1 = (const char*)g_vbu[1];

    // Q load (hi/lo), rows are 128 B in gmem
    #pragma unroll
    for (int it = 0; it < 4; it++) {
        int idx = it * 256 + tid;
        int row = idx >> 3, ch = idx & 7;
        size_t so = (size_t)(bh * 2048 + qi * 128 + row) * 128 + ch * 16;
        uint32_t d = (uint32_t)row * 144 + ch * 16;
        cp16(sb + d,         qs0 + so);
        cp16(sb + 18432 + d, qs1 + so);
    }
    CP_COMMIT();

    float oacc[8][4] = {};
    float m0 = -1e30f, m1 = -1e30f, l0 = 0.f, l1 = 0.f;

    const uint32_t offA  = sb + (uint32_t)(wid * 16 + lrow + ((lane >> 3) & 1) * 8) * 144
                              + ((lane >> 4) & 1) * 16;
    const uint32_t offKB = sb + 36864 + (uint32_t)(lrow + ((lane >> 4) & 1) * 8) * 144
                              + ((lane >> 3) & 1) * 16;
    const uint32_t offVB = sb + 73728 + (uint32_t)(lrow + ((lane >> 3) & 1) * 8) * 144
                              + ((lane >> 4) & 1) * 16;

    const int r0 = wid * 16 + g;
    const int r1 = r0 + 8;

    for (int kb = 0; kb <= qi; kb++) {
        __syncthreads();   // smem reuse guard
        #pragma unroll
        for (int it = 0; it < 4; it++) {
            int idx = it * 256 + tid;
            int row = idx >> 3, ch = idx & 7;
            size_t so = (size_t)(bh * 2048 + kb * 128 + row) * 128 + ch * 16;
            uint32_t d = (uint32_t)row * 144 + ch * 16;
            cp16(sb + 36864 + d, ks0 + so);
            cp16(sb + 55296 + d, ks1 + so);
            cp16(sb + 73728 + d, vs0 + so);
            cp16(sb + 92160 + d, vs1 + so);
        }
        CP_COMMIT(); CP_WAIT0(); __syncthreads();

        // S = Q K^T (3-term bf16 split; scale folded into Q)
        float sacc[16][4];
        #pragma unroll
        for (int nt = 0; nt < 16; nt++)
            #pragma unroll
            for (int j = 0; j < 4; j++) sacc[nt][j] = 0.f;

        #pragma unroll
        for (int s = 0; s < 4; s++) {
            uint32_t ah[4], al[4];
            LDSM_X4(ah[0], ah[1], ah[2], ah[3], offA + s * 32);
            LDSM_X4(al[0], al[1], al[2], al[3], offA + 18432 + s * 32);
            #pragma unroll
            for (int p = 0; p < 8; p++) {
                uint32_t kh[2][2], kl[2][2];
                LDSM_X4(kh[0][0], kh[0][1], kh[1][0], kh[1][1],
                        offKB + p * 2304 + s * 32);
                LDSM_X4(kl[0][0], kl[0][1], kl[1][0], kl[1][1],
                        offKB + 18432 + p * 2304 + s * 32);
                mma_bf16(sacc[2*p],     ah, kh[0]);
                mma_bf16(sacc[2*p],     ah, kl[0]);
                mma_bf16(sacc[2*p],     al, kh[0]);
                mma_bf16(sacc[2*p+1],   ah, kh[1]);
                mma_bf16(sacc[2*p+1],   ah, kl[1]);
                mma_bf16(sacc[2*p+1],   al, kh[1]);
            }
        }

        // causal mask (diagonal key tile only)
        if (kb == qi) {
            #pragma unroll
            for (int nt = 0; nt < 16; nt++) {
                int cb = nt * 8 + 2 * tig;
                if (cb     > r0) sacc[nt][0] = -1e30f;
                if (cb + 1 > r0) sacc[nt][1] = -1e30f;
                if (cb     > r1) sacc[nt][2] = -1e30f;
                if (cb + 1 > r1) sacc[nt][3] = -1e30f;
            }
        }

        // online softmax (rows r0, r1; full row lives in 4-lane quad)
        float t0 = -1e30f, t1 = -1e30f;
        #pragma unroll
        for (int nt = 0; nt < 16; nt++) {
            t0 = fmaxf(t0, fmaxf(sacc[nt][0], sacc[nt][1]));
            t1 = fmaxf(t1, fmaxf(sacc[nt][2], sacc[nt][3]));
        }
        t0 = fmaxf(t0, __shfl_xor_sync(0xffffffffu, t0, 1));
        t0 = fmaxf(t0, __shfl_xor_sync(0xffffffffu, t0, 2));
        t1 = fmaxf(t1, __shfl_xor_sync(0xffffffffu, t1, 1));
        t1 = fmaxf(t1, __shfl_xor_sync(0xffffffffu, t1, 2));
        float mn0 = fmaxf(m0, t0), mn1 = fmaxf(m1, t1);
        float c0 = __expf(m0 - mn0), c1 = __expf(m1 - mn1);
        l0 *= c0; l1 *= c1;
        #pragma unroll
        for (int nt = 0; nt < 8; nt++) {
            oacc[nt][0] *= c0; oacc[nt][1] *= c0;
            oacc[nt][2] *= c1; oacc[nt][3] *= c1;
        }
        float ps0 = 0.f, ps1 = 0.f;
        #pragma unroll
        for (int nt = 0; nt < 16; nt++) {
            sacc[nt][0] = __expf(sacc[nt][0] - mn0); ps0 += sacc[nt][0];
            sacc[nt][1] = __expf(sacc[nt][1] - mn0); ps0 += sacc[nt][1];
            sacc[nt][2] = __expf(sacc[nt][2] - mn1); ps1 += sacc[nt][2];
            sacc[nt][3] = __expf(sacc[nt][3] - mn1); ps1 += sacc[nt][3];
        }
        ps0 += __shfl_xor_sync(0xffffffffu, ps0, 1);
        ps0 += __shfl_xor_sync(0xffffffffu, ps0, 2);
        ps1 += __shfl_xor_sync(0xffffffffu, ps1, 1);
        ps1 += __shfl_xor_sync(0xffffffffu, ps1, 2);
        l0 += ps0; l1 += ps1;
        m0 = mn0; m1 = mn1;

        // O += P V (P packed from S accumulators; V frags via ldmatrix.trans)
        #pragma unroll
        for (int s = 0; s < 8; s++) {
            uint32_t pah[4], pal[4];
            split2(sacc[2*s][0],   sacc[2*s][1],   pah[0], pal[0]);
            split2(sacc[2*s][2],   sacc[2*s][3],   pah[1], pal[1]);
            split2(sacc[2*s+1][0], sacc[2*s+1][1], pah[2], pal[2]);
            split2(sacc[2*s+1][2], sacc[2*s+1][3], pah[3], pal[3]);
            #pragma unroll
            for (int p = 0; p < 4; p++) {
                uint32_t vh[2][2], vl[2][2];
                LDSM_X4_T(vh[0][0], vh[0][1], vh[1][0], vh[1][1],
                          offVB + s * 2304 + p * 32);
                LDSM_X4_T(vl[0][0], vl[0][1], vl[1][0], vl[1][1],
                          offVB + 18432 + s * 2304 + p * 32);
                mma_bf16(oacc[2*p],   pah, vh[0]);
                mma_bf16(oacc[2*p],   pah, vl[0]);
                mma_bf16(oacc[2*p],   pal, vh[0]);
                mma_bf16(oacc[2*p+1], pah, vh[1]);
                mma_bf16(oacc[2*p+1], pah, vl[1]);
                mma_bf16(oacc[2*p+1], pal, vh[1]);
            }
        }
    }

    // Epilogue: write O (hi/lo tiled) into g_at for the proj GEMM
    float inv0 = 1.f / l0, inv1 = 1.f / l1;
    const int b_ = bh >> 4, h_ = bh & 15;
    #pragma unroll
    for (int nt = 0; nt < 8; nt++) {
        int dcol = nt * 8 + 2 * tig;
        int k = h_ * 64 + dcol;
        int c = k >> 5, kk = k & 31, s_ = kk >> 3;
        int w = (kk & 7) >> 1;
        int m = b_ * 2048 + qi * 128 + r0;
        {
            uint32_t hi, lo;
            split2(oacc[nt][0] * inv0, oacc[nt][1] * inv0, hi, lo);
            int tile = m >> 7, mloc = m & 127;
            size_t u4 = ((size_t)(tile * 32 + c) * 4 + s_) * 128 + mloc;
            *reinterpret_cast<uint32_t*>(reinterpret_cast<char*>(&g_at[0][u4]) + w * 4) = hi;
            *reinterpret_cast<uint32_t*>(reinterpret_cast<char*>(&g_at[1][u4]) + w * 4) = lo;
        }
        m += 8;
        {
            uint32_t hi, lo;
            split2(oacc[nt][2] * inv1, oacc[nt][3] * inv1, hi, lo);
            int tile = m >> 7, mloc = m & 127;
            size_t u4 = ((size_t)(tile * 32 + c) * 4 + s_) * 128 + mloc;
            *reinterpret_cast<uint32_t*>(reinterpret_cast<char*>(&g_at[0][u4]) + w * 4) = hi;
            *reinterpret_cast<uint32_t*>(reinterpret_cast<char*>(&g_at[1][u4]) + w * 4) = lo;
        }
    }
}

// ---------------------------------------------------------------------------
extern "C" void kernel_launch(void* const* d_in, const int* in_sizes, int n_in,
                              void* d_out, int out_size)
{
    const float* x    = (const float*)d_in[0];
    const float* Wqkv = (const float*)d_in[1];
    const float* bqkv = (const float*)d_in[2];
    const float* Wout = (const float*)d_in[3];
    const float* bout = (const float*)d_in[4];

    float* out  = (float*)d_out;
    float* kout = out + BTC;
    float* vout = out + 2 * BTC;

    // Pre-pass conversions
    convert_x_kernel<<<8192, 256>>>(x);
    convert_w_kernel<<<dim3(32, 96), 256>>>(Wqkv, N1, 0);
    convert_w_kernel<<<dim3(32, 32), 256>>>(Wout, C, 24);

    cudaFuncSetAttribute(mma_gemm, cudaFuncAttributeMaxDynamicSharedMemorySize,
                         GEMM_SMEM);
    cudaFuncSetAttribute(attn_kernel, cudaFuncAttributeMaxDynamicSharedMemorySize,
                         ATTN_SMEM);

    // 1) QKV projection (also emits bf16 hi/lo q/k/v scratch)
    mma_gemm<<<dim3(N1 / 128, M1 / 128), 256, GEMM_SMEM>>>(
        bqkv, nullptr, kout, vout, 0);

    // 2) causal flash attention (tensor cores)
    attn_kernel<<<dim3(T / 128, B * H), 256, ATTN_SMEM>>>();

    // 3) output projection
    mma_gemm<<<dim3(C / 128, M1 / 128), 256, GEMM_SMEM>>>(
        bout, out, nullptr, nullptr, 1);
}